// round 15
// baseline (speedup 1.0000x reference)
#include <cuda_runtime.h>
#include <math.h>

#define NCLS 21
#define C    256
#define HW   16384
#define B    8
#define NPIX (B*HW)
#define CAPW 2048
#define CAPS 8192
#define EPSF 1e-6f
#define NBINS 4096
#define BCAP 1024
#define PSTR 257
#define WCH  32
#define LGRID (NCLS*32)   // 672 loss blocks

// ---------------- device scratch (zero-init at load; finalize restores) -----
__device__ float g_wsum[NCLS*C];
__device__ int   g_cnt_w[NCLS];
__device__ int   g_cnt_s[NCLS];
__device__ unsigned long long g_wkeys[NCLS*CAPW];
__device__ unsigned long long g_skeys[NCLS*CAPS];
__device__ int   g_sidx[NCLS*256];
__device__ int   g_kw[NCLS];
__device__ int   g_ks[NCLS];
__device__ float g_wn[NCLS*C*16];
__device__ unsigned g_maxv[NCLS*16];
__device__ int   g_done;

__device__ __forceinline__ unsigned long long make_key(float v, int idx) {
    unsigned u = __float_as_uint(v);
    u = (u & 0x80000000u) ? ~u : (u | 0x80000000u);
    return ((unsigned long long)u << 32) | (unsigned long long)(0xFFFFFFFFu - (unsigned)idx);
}
__device__ __forceinline__ int key_idx(unsigned long long k) {
    return (int)(0xFFFFFFFFu - (unsigned)(k & 0xFFFFFFFFull));
}
__device__ __forceinline__ unsigned fenc(float f) {
    unsigned u = __float_as_uint(f);
    return (u >> 31) ? ~u : (u | 0x80000000u);
}
__device__ __forceinline__ float fdec(unsigned u) {
    return __uint_as_float((u >> 31) ? (u & 0x7FFFFFFFu) : ~u);
}

// ---------------- K1: fused per-pixel pass (R2-proven form) ----------------
__global__ __launch_bounds__(256) void main_kernel(
    const float* __restrict__ fw, const float* __restrict__ fs,
    const float* __restrict__ prob, const int* __restrict__ pred,
    const int* __restrict__ ign, const float* __restrict__ bank)
{
    __shared__ float spn[NCLS*PSTR];
    __shared__ int scw[NCLS], scs[NCLS], sbw[NCLS], sbs[NCLS];
    int t = threadIdx.x, w = t >> 5, l = t & 31;

    for (int k = w; k < NCLS; k += 8) {
        float v[8]; float s2 = 0.f;
        #pragma unroll
        for (int i = 0; i < 8; i++) { v[i] = bank[k*C + l + 32*i]; s2 = fmaf(v[i], v[i], s2); }
        #pragma unroll
        for (int o = 16; o; o >>= 1) s2 += __shfl_xor_sync(0xFFFFFFFFu, s2, o);
        float inv = 1.0f / fmaxf(sqrtf(s2), EPSF);
        #pragma unroll
        for (int i = 0; i < 8; i++) spn[k*PSTR + l + 32*i] = v[i] * inv;
    }
    if (t < NCLS) { scw[t] = 0; scs[t] = 0; }
    __syncthreads();

    int n0 = blockIdx.x*512 + t, n1 = n0 + 256;
    int b0 = n0 >> 14, p0 = n0 & (HW-1);
    int b1 = n1 >> 14, p1 = n1 & (HW-1);
    int seg0 = pred[n0], seg1 = pred[n1];
    bool valid0 = (ign[n0] != 255), valid1 = (ign[n1] != 255);
    bool conf0 = valid0 && (prob[n0] > 0.95f);
    bool conf1 = valid1 && (prob[n1] > 0.95f);

    const float* bw0 = fw + (size_t)b0*C*HW + p0;
    const float* bs0 = fs + (size_t)b0*C*HW + p0;
    const float* bw1 = fw + (size_t)b1*C*HW + p1;
    const float* bs1 = fs + (size_t)b1*C*HW + p1;
    const float* pr0 = spn + seg0*PSTR;
    const float* pr1 = spn + seg1*PSTR;

    float dw0=0.f, ds0=0.f, qw0=0.f, qs0=0.f;
    float dw1=0.f, ds1=0.f, qw1=0.f, qs1=0.f;
    #pragma unroll 8
    for (int c = 0; c < C; c++) {
        float vw0 = bw0[(size_t)c*HW], vs0 = bs0[(size_t)c*HW];
        float vw1 = bw1[(size_t)c*HW], vs1 = bs1[(size_t)c*HW];
        float pv0 = pr0[c], pv1 = pr1[c];
        dw0 = fmaf(vw0, pv0, dw0);  qw0 = fmaf(vw0, vw0, qw0);
        ds0 = fmaf(vs0, pv0, ds0);  qs0 = fmaf(vs0, vs0, qs0);
        dw1 = fmaf(vw1, pv1, dw1);  qw1 = fmaf(vw1, vw1, qw1);
        ds1 = fmaf(vs1, pv1, ds1);  qs1 = fmaf(vs1, vs1, qs1);
    }
    float simw0 = dw0 / fmaxf(sqrtf(qw0), EPSF);
    float sims0 = ds0 / fmaxf(sqrtf(qs0), EPSF);
    float simw1 = dw1 / fmaxf(sqrtf(qw1), EPSF);
    float sims1 = ds1 / fmaxf(sqrtf(qs1), EPSF);

    int lw0=-1, ls0=-1, lw1=-1, ls1=-1;
    if (conf0)  lw0 = atomicAdd(&scw[seg0], 1);
    if (conf1)  lw1 = atomicAdd(&scw[seg1], 1);
    if (valid0) ls0 = atomicAdd(&scs[seg0], 1);
    if (valid1) ls1 = atomicAdd(&scs[seg1], 1);
    __syncthreads();
    if (t < NCLS) {
        sbw[t] = atomicAdd(&g_cnt_w[t], scw[t]);
        sbs[t] = atomicAdd(&g_cnt_s[t], scs[t]);
    }
    __syncthreads();
    if (conf0)  { int pos = sbw[seg0] + lw0; if (pos < CAPW) g_wkeys[seg0*CAPW + pos] = make_key(simw0, n0); }
    if (conf1)  { int pos = sbw[seg1] + lw1; if (pos < CAPW) g_wkeys[seg1*CAPW + pos] = make_key(simw1, n1); }
    if (valid0) { int pos = sbs[seg0] + ls0; if (pos < CAPS) g_skeys[seg0*CAPS + pos] = make_key(-sims0, n0); }
    if (valid1) { int pos = sbs[seg1] + ls1; if (pos < CAPS) g_skeys[seg1*CAPS + pos] = make_key(-sims1, n1); }
}

// ---------------- K2: selection + wsum gather (42 + 672 blocks) -------------
__global__ __launch_bounds__(256) void select_kernel(const float* __restrict__ fw) {
    __shared__ unsigned long long skeys[2048];
    __shared__ int hist[NBINS];
    __shared__ unsigned long long bkeys[BCAP];
    __shared__ int gsum[256];
    __shared__ int sh_T, sh_a, sh_m, sh_out, sh_bnd;

    int blk = blockIdx.x, tid = threadIdx.x;
    if (blk >= 2*NCLS) {
        // ---- wsum gather (fills idle SMs while 42 select blocks run) ----
        int wb = blk - 2*NCLS;
        int k = wb >> 5, ch = wb & (WCH-1);
        int cnt = g_cnt_w[k]; if (cnt > CAPW) cnt = CAPW;
        int per = (cnt + WCH - 1) / WCH;
        int lo = ch * per, hi = lo + per; if (hi > cnt) hi = cnt;
        if (hi <= lo) return;
        const unsigned long long* wk = &g_wkeys[k*CAPW];
        float a0=0.f,a1=0.f,a2=0.f,a3=0.f,a4=0.f,a5=0.f,a6=0.f,a7=0.f;
        int i = lo;
        for (; i + 8 <= hi; i += 8) {
            int m0 = key_idx(wk[i]),   m1 = key_idx(wk[i+1]);
            int m2 = key_idx(wk[i+2]), m3 = key_idx(wk[i+3]);
            int m4 = key_idx(wk[i+4]), m5 = key_idx(wk[i+5]);
            int m6 = key_idx(wk[i+6]), m7 = key_idx(wk[i+7]);
            a0 += fw[(((size_t)(m0 >> 14))*C + tid)*HW + (m0 & (HW-1))];
            a1 += fw[(((size_t)(m1 >> 14))*C + tid)*HW + (m1 & (HW-1))];
            a2 += fw[(((size_t)(m2 >> 14))*C + tid)*HW + (m2 & (HW-1))];
            a3 += fw[(((size_t)(m3 >> 14))*C + tid)*HW + (m3 & (HW-1))];
            a4 += fw[(((size_t)(m4 >> 14))*C + tid)*HW + (m4 & (HW-1))];
            a5 += fw[(((size_t)(m5 >> 14))*C + tid)*HW + (m5 & (HW-1))];
            a6 += fw[(((size_t)(m6 >> 14))*C + tid)*HW + (m6 & (HW-1))];
            a7 += fw[(((size_t)(m7 >> 14))*C + tid)*HW + (m7 & (HW-1))];
        }
        for (; i < hi; i++) {
            int m0 = key_idx(wk[i]);
            a0 += fw[(((size_t)(m0 >> 14))*C + tid)*HW + (m0 & (HW-1))];
        }
        atomicAdd(&g_wsum[k*C + tid], ((a0+a1)+(a2+a3)) + ((a4+a5)+(a6+a7)));
        return;
    }
    if (blk < NCLS) {
        // ---- weak: dynamic-size bitonic sort desc + rank-mapped gather/normalize
        int k = blk;
        int cnt = g_cnt_w[k]; if (cnt > CAPW) cnt = CAPW;
        int P = 32; while (P < cnt) P <<= 1;
        for (int i = tid; i < P; i += 256)
            skeys[i] = (i < cnt) ? g_wkeys[k*CAPW + i] : 0ull;
        __syncthreads();
        for (int kk = 2; kk <= P; kk <<= 1) {
            for (int j = kk >> 1; j > 0; j >>= 1) {
                for (int i = tid; i < P; i += 256) {
                    int ixj = i ^ j;
                    if (ixj > i) {
                        unsigned long long a = skeys[i], bb = skeys[ixj];
                        bool up = ((i & kk) == 0);
                        if (up ? (a < bb) : (a > bb)) { skeys[i] = bb; skeys[ixj] = a; }
                    }
                }
                __syncthreads();
            }
        }
        int kw = (cnt < 16) ? cnt : 16;
        if (tid == 0) g_kw[k] = kw;
        int w = tid >> 5, l = tid & 31;
        #pragma unroll
        for (int rb = 0; rb < 2; rb++) {
            int r = w + rb*8;
            int rr = (r == 0) ? 0 : (r - 1);
            float v[8]; float s2 = 0.f;
            if (r < kw) {
                int n = key_idx(skeys[rr]);
                int b = n >> 14, p = n & (HW-1);
                const float* base = fw + (size_t)b*C*HW + p;
                #pragma unroll
                for (int i = 0; i < 8; i++) {
                    v[i] = base[(size_t)(l + 32*i)*HW];
                    s2 = fmaf(v[i], v[i], s2);
                }
            } else {
                #pragma unroll
                for (int i = 0; i < 8; i++) v[i] = 0.f;
            }
            #pragma unroll
            for (int o = 16; o; o >>= 1) s2 += __shfl_xor_sync(0xFFFFFFFFu, s2, o);
            float inv = 1.0f / fmaxf(sqrtf(s2), EPSF);
            #pragma unroll
            for (int i = 0; i < 8; i++)
                g_wn[(k*C + l + 32*i)*16 + r] = v[i] * inv;
        }
    } else {
        // ---- strong: radix select top-256 set (unordered) ----
        int k = blk - NCLS;
        int cnt = g_cnt_s[k]; if (cnt > CAPS) cnt = CAPS;
        int need = (cnt < 256) ? cnt : 256;
        for (int i = tid; i < NBINS; i += 256) hist[i] = 0;
        if (tid == 0) { sh_out = 0; sh_bnd = 0; }
        __syncthreads();
        const unsigned long long* src = &g_skeys[k*CAPS];
        for (int i = tid; i < cnt; i += 256) {
            int bin = (int)(src[i] >> 52);
            atomicAdd(&hist[bin], 1);
        }
        __syncthreads();
        { int s = 0;
          #pragma unroll 4
          for (int b2 = 0; b2 < 16; b2++) s += hist[tid*16 + b2];
          gsum[tid] = s; }
        __syncthreads();
        if (tid == 0) {
            int acc = 0, G = 0;
            for (int g = 255; g >= 0; g--) {
                if (acc + gsum[g] >= need) { G = g; break; }
                acc += gsum[g];
            }
            int T = G*16;
            for (int b2 = G*16 + 15; b2 >= G*16; b2--) {
                if (acc + hist[b2] >= need) { T = b2; break; }
                acc += hist[b2];
            }
            sh_T = T; sh_a = acc; sh_m = need - acc;
        }
        __syncthreads();
        int T = sh_T;
        for (int i = tid; i < cnt; i += 256) {
            unsigned long long key = src[i];
            int bin = (int)(key >> 52);
            if (bin > T) {
                int pos = atomicAdd(&sh_out, 1);
                g_sidx[k*256 + pos] = key_idx(key);
            } else if (bin == T) {
                int pos = atomicAdd(&sh_bnd, 1);
                if (pos < BCAP) bkeys[pos] = key;
            }
        }
        __syncthreads();
        int bnd = sh_bnd; if (bnd > BCAP) bnd = BCAP;
        int P = 1; while (P < bnd) P <<= 1;
        for (int i = tid; i < P; i += 256) if (i >= bnd) bkeys[i] = 0ull;
        __syncthreads();
        for (int kk = 2; kk <= P; kk <<= 1) {
            for (int j = kk >> 1; j > 0; j >>= 1) {
                for (int i = tid; i < P; i += 256) {
                    int ixj = i ^ j;
                    if (ixj > i) {
                        unsigned long long a = bkeys[i], bb = bkeys[ixj];
                        bool up = ((i & kk) == 0);
                        if (up ? (a < bb) : (a > bb)) { bkeys[i] = bb; bkeys[ixj] = a; }
                    }
                }
                __syncthreads();
            }
        }
        if (tid < sh_m) g_sidx[k*256 + sh_a + tid] = key_idx(bkeys[tid]);
        if (tid == 0) g_ks[k] = need;
    }
}

// ---------------- K3: loss (21x32 warp-per-slot) + fused finalize -----------
__global__ __launch_bounds__(256) void loss_kernel(
    const float* __restrict__ fs, const float* __restrict__ bank,
    float* __restrict__ out, int out_size)
{
    int k = blockIdx.x, chunk = blockIdx.y, tid = threadIdx.x;
    __shared__ float swn[C*18];
    __shared__ unsigned smax[16];
    __shared__ float sred[256];
    __shared__ int scnt[256];
    __shared__ int slast;
    for (int i = tid; i < C*16; i += 256) {
        int c = i >> 4, r = i & 15;
        swn[c*18 + r] = g_wn[k*C*16 + i];
    }
    if (tid < 16) smax[tid] = 0u;
    __syncthreads();

    int ks = g_ks[k];
    int w = tid >> 5, lane = tid & 31;   // warp = slot
    int s = chunk*8 + w;

    float acc[16];
    #pragma unroll
    for (int r = 0; r < 16; r++) acc[r] = 0.f;
    float q = 0.f;
    bool active = (s < ks);
    if (active) {
        int n = g_sidx[k*256 + s];
        int b = n >> 14, p = n & (HW-1);
        const float* base = fs + (size_t)b*C*HW + p;
        #pragma unroll
        for (int cc = 0; cc < 8; cc++) {
            int c = cc*32 + lane;
            float v = base[(size_t)c*HW];
            q = fmaf(v, v, q);
            const float2* row = (const float2*)&swn[c*18];
            #pragma unroll
            for (int g = 0; g < 8; g++) {
                float2 w2 = row[g];
                acc[g*2+0] = fmaf(v, w2.x, acc[g*2+0]);
                acc[g*2+1] = fmaf(v, w2.y, acc[g*2+1]);
            }
        }
    }
    // split-butterfly: 16 accs across 32 lanes in 16 shfl (+5 for q)
    #pragma unroll
    for (int j = 0; j < 8; j++) {
        float send = (lane & 16) ? acc[j] : acc[j+8];
        float keep = (lane & 16) ? acc[j+8] : acc[j];
        acc[j] = keep + __shfl_xor_sync(0xFFFFFFFFu, send, 16);
    }
    #pragma unroll
    for (int j = 0; j < 4; j++) {
        float send = (lane & 8) ? acc[j] : acc[j+4];
        float keep = (lane & 8) ? acc[j+4] : acc[j];
        acc[j] = keep + __shfl_xor_sync(0xFFFFFFFFu, send, 8);
    }
    #pragma unroll
    for (int j = 0; j < 2; j++) {
        float send = (lane & 4) ? acc[j] : acc[j+2];
        float keep = (lane & 4) ? acc[j+2] : acc[j];
        acc[j] = keep + __shfl_xor_sync(0xFFFFFFFFu, send, 4);
    }
    {
        float send = (lane & 2) ? acc[0] : acc[1];
        float keep = (lane & 2) ? acc[1] : acc[0];
        acc[0] = keep + __shfl_xor_sync(0xFFFFFFFFu, send, 2);
    }
    acc[0] += __shfl_xor_sync(0xFFFFFFFFu, acc[0], 1);
    #pragma unroll
    for (int o = 16; o; o >>= 1) q += __shfl_xor_sync(0xFFFFFFFFu, q, o);
    // lane L (L even) holds total for r = (L>>1): bit map {16->8, 8->4, 4->2, 2->1}
    if (active && (lane & 1) == 0) {
        float inv = 1.0f / fmaxf(sqrtf(q), EPSF);
        int r = ((lane & 16) >> 1) | ((lane & 8) >> 1) | ((lane & 4) >> 1) | ((lane & 2) >> 1);
        atomicMax(&smax[r], fenc(acc[0] * inv));
    }
    __syncthreads();
    if (tid < 16 && ks > 0) atomicMax(&g_maxv[k*16 + tid], smax[tid]);

    // ---- last-block-done finalize (replaces final_kernel) ----
    __threadfence();
    if (tid == 0) slast = (atomicAdd(&g_done, 1) == LGRID - 1) ? 1 : 0;
    __syncthreads();
    if (!slast) return;

    // EMA memory-bank update + wsum restore
    for (int i = tid; i < NCLS*C; i += 256) {
        int kk = i >> 8;
        int nw = g_cnt_w[kk];
        float pv = bank[i];
        float o = pv;
        if (nw > 0) {
            float mean = g_wsum[i] / (float)((nw > 1) ? nw : 1);
            o = 0.99f * pv + 0.01f * mean;
        }
        if ((1 + i) < out_size) out[1 + i] = o;
        g_wsum[i] = 0.f;
    }
    // parallel loss reduction over 21*16 slots
    {
        float ssum = 0.f;
        int cnt = 0;
        for (int idx = tid; idx < NCLS*16; idx += 256) {
            int kk = idx >> 4, r = idx & 15;
            int kw = g_kw[kk], kss = g_ks[kk];
            if (kw > 0 && kss > 0) {
                if (r < kw) ssum += fdec(g_maxv[idx]);
                if (r == 0) cnt += kss;
            }
        }
        sred[tid] = ssum;
        scnt[tid] = cnt;
        __syncthreads();
        #pragma unroll
        for (int o = 128; o; o >>= 1) {
            if (tid < o) { sred[tid] += sred[tid + o]; scnt[tid] += scnt[tid + o]; }
            __syncthreads();
        }
        if (tid == 0)
            out[0] = (scnt[0] > 0) ? (1.0f - sred[0] / (float)scnt[0]) : 0.0f;
        __syncthreads();
    }
    // restore remaining scratch for next graph replay
    for (int idx = tid; idx < NCLS*16; idx += 256) g_maxv[idx] = 0u;
    if (tid < NCLS) { g_cnt_w[tid] = 0; g_cnt_s[tid] = 0; }
    if (tid == 0) g_done = 0;
}

// ---------------- launch ----------------
extern "C" void kernel_launch(void* const* d_in, const int* in_sizes, int n_in,
                              void* d_out, int out_size) {
    const float* fw   = (const float*)d_in[0];
    const float* fs   = (const float*)d_in[1];
    const float* prob = (const float*)d_in[2];
    const float* bank = (const float*)d_in[3];
    const int*   pred = (const int*)d_in[4];
    const int*   ign  = (const int*)d_in[5];
    float* out = (float*)d_out;

    main_kernel<<<NPIX/512, 256>>>(fw, fs, prob, pred, ign, bank);
    select_kernel<<<2*NCLS + NCLS*WCH, 256>>>(fw);
    loss_kernel<<<dim3(NCLS, 32), 256>>>(fs, bank, out, out_size);
}

// round 16
// speedup vs baseline: 1.2619x; 1.2619x over previous
#include <cuda_runtime.h>
#include <math.h>

#define NCLS 21
#define C    256
#define HW   16384
#define B    8
#define NPIX (B*HW)
#define CAPW 2048
#define CAPS 8192
#define EPSF 1e-6f
#define NBINS 4096
#define BCAP 1024
#define PSTR 257
#define WCH  32

// ---------------- device scratch (zero-init at load; final_kernel restores) --
__device__ float g_wsum[NCLS*C];
__device__ int   g_cnt_w[NCLS];
__device__ int   g_cnt_s[NCLS];
__device__ unsigned long long g_wkeys[NCLS*CAPW];
__device__ unsigned long long g_skeys[NCLS*CAPS];
__device__ int   g_sidx[NCLS*256];
__device__ int   g_kw[NCLS];
__device__ int   g_ks[NCLS];
__device__ float g_wn[NCLS*C*16];
__device__ unsigned g_maxv[NCLS*16];

__device__ __forceinline__ unsigned long long make_key(float v, int idx) {
    unsigned u = __float_as_uint(v);
    u = (u & 0x80000000u) ? ~u : (u | 0x80000000u);
    return ((unsigned long long)u << 32) | (unsigned long long)(0xFFFFFFFFu - (unsigned)idx);
}
__device__ __forceinline__ int key_idx(unsigned long long k) {
    return (int)(0xFFFFFFFFu - (unsigned)(k & 0xFFFFFFFFull));
}
__device__ __forceinline__ unsigned fenc(float f) {
    unsigned u = __float_as_uint(f);
    return (u >> 31) ? ~u : (u | 0x80000000u);
}
__device__ __forceinline__ float fdec(unsigned u) {
    return __uint_as_float((u >> 31) ? (u & 0x7FFFFFFFu) : ~u);
}

// ---------------- K1: fused per-pixel pass (1 pixel/thread, grid 512) -------
__global__ __launch_bounds__(256) void main_kernel(
    const float* __restrict__ fw, const float* __restrict__ fs,
    const float* __restrict__ prob, const int* __restrict__ pred,
    const int* __restrict__ ign, const float* __restrict__ bank)
{
    __shared__ float spn[NCLS*PSTR];
    __shared__ int scw[NCLS], scs[NCLS], sbw[NCLS], sbs[NCLS];
    int t = threadIdx.x, w = t >> 5, l = t & 31;

    for (int k = w; k < NCLS; k += 8) {
        float v[8]; float s2 = 0.f;
        #pragma unroll
        for (int i = 0; i < 8; i++) { v[i] = bank[k*C + l + 32*i]; s2 = fmaf(v[i], v[i], s2); }
        #pragma unroll
        for (int o = 16; o; o >>= 1) s2 += __shfl_xor_sync(0xFFFFFFFFu, s2, o);
        float inv = 1.0f / fmaxf(sqrtf(s2), EPSF);
        #pragma unroll
        for (int i = 0; i < 8; i++) spn[k*PSTR + l + 32*i] = v[i] * inv;
    }
    if (t < NCLS) { scw[t] = 0; scs[t] = 0; }
    __syncthreads();

    int n = blockIdx.x*256 + t;
    int b = n >> 14, p = n & (HW-1);
    int seg = pred[n];
    bool valid = (ign[n] != 255);
    bool conf  = valid && (prob[n] > 0.95f);

    const float* bw = fw + (size_t)b*C*HW + p;
    const float* bs = fs + (size_t)b*C*HW + p;
    const float* pr = spn + seg*PSTR;

    float dw = 0.f, ds = 0.f, qw = 0.f, qs = 0.f;
    #pragma unroll 8
    for (int c = 0; c < C; c++) {
        float vw = bw[(size_t)c*HW];
        float vs = bs[(size_t)c*HW];
        float pv = pr[c];
        dw = fmaf(vw, pv, dw);  qw = fmaf(vw, vw, qw);
        ds = fmaf(vs, pv, ds);  qs = fmaf(vs, vs, qs);
    }
    float simw = dw / fmaxf(sqrtf(qw), EPSF);
    float sims = ds / fmaxf(sqrtf(qs), EPSF);

    int lw = -1, ls = -1;
    if (conf)  lw = atomicAdd(&scw[seg], 1);
    if (valid) ls = atomicAdd(&scs[seg], 1);
    __syncthreads();
    if (t < NCLS) {
        sbw[t] = atomicAdd(&g_cnt_w[t], scw[t]);
        sbs[t] = atomicAdd(&g_cnt_s[t], scs[t]);
    }
    __syncthreads();
    if (conf)  { int pos = sbw[seg] + lw; if (pos < CAPW) g_wkeys[seg*CAPW + pos] = make_key(simw, n); }
    if (valid) { int pos = sbs[seg] + ls; if (pos < CAPS) g_skeys[seg*CAPS + pos] = make_key(-sims, n); }
}

// ---------------- K2: selection + wsum gather (42 + 672 blocks) -------------
__global__ __launch_bounds__(256) void select_kernel(const float* __restrict__ fw) {
    __shared__ unsigned long long skeys[2048];
    __shared__ int hist[NBINS];
    __shared__ unsigned long long bkeys[BCAP];
    __shared__ int gsum[256];
    __shared__ int sh_T, sh_a, sh_m, sh_out, sh_bnd;

    int blk = blockIdx.x, tid = threadIdx.x;
    if (blk >= 2*NCLS) {
        // ---- wsum gather (fills idle SMs while 42 select blocks run) ----
        int wb = blk - 2*NCLS;
        int k = wb >> 5, ch = wb & (WCH-1);
        int cnt = g_cnt_w[k]; if (cnt > CAPW) cnt = CAPW;
        int per = (cnt + WCH - 1) / WCH;
        int lo = ch * per, hi = lo + per; if (hi > cnt) hi = cnt;
        if (hi <= lo) return;
        const unsigned long long* wk = &g_wkeys[k*CAPW];
        float a0=0.f,a1=0.f,a2=0.f,a3=0.f,a4=0.f,a5=0.f,a6=0.f,a7=0.f;
        int i = lo;
        for (; i + 8 <= hi; i += 8) {
            int m0 = key_idx(wk[i]),   m1 = key_idx(wk[i+1]);
            int m2 = key_idx(wk[i+2]), m3 = key_idx(wk[i+3]);
            int m4 = key_idx(wk[i+4]), m5 = key_idx(wk[i+5]);
            int m6 = key_idx(wk[i+6]), m7 = key_idx(wk[i+7]);
            a0 += fw[(((size_t)(m0 >> 14))*C + tid)*HW + (m0 & (HW-1))];
            a1 += fw[(((size_t)(m1 >> 14))*C + tid)*HW + (m1 & (HW-1))];
            a2 += fw[(((size_t)(m2 >> 14))*C + tid)*HW + (m2 & (HW-1))];
            a3 += fw[(((size_t)(m3 >> 14))*C + tid)*HW + (m3 & (HW-1))];
            a4 += fw[(((size_t)(m4 >> 14))*C + tid)*HW + (m4 & (HW-1))];
            a5 += fw[(((size_t)(m5 >> 14))*C + tid)*HW + (m5 & (HW-1))];
            a6 += fw[(((size_t)(m6 >> 14))*C + tid)*HW + (m6 & (HW-1))];
            a7 += fw[(((size_t)(m7 >> 14))*C + tid)*HW + (m7 & (HW-1))];
        }
        for (; i < hi; i++) {
            int m0 = key_idx(wk[i]);
            a0 += fw[(((size_t)(m0 >> 14))*C + tid)*HW + (m0 & (HW-1))];
        }
        atomicAdd(&g_wsum[k*C + tid], ((a0+a1)+(a2+a3)) + ((a4+a5)+(a6+a7)));
        return;
    }
    if (blk < NCLS) {
        // ---- weak: dynamic-size bitonic sort desc + rank-mapped gather/normalize
        int k = blk;
        int cnt = g_cnt_w[k]; if (cnt > CAPW) cnt = CAPW;
        int P = 32; while (P < cnt) P <<= 1;
        for (int i = tid; i < P; i += 256)
            skeys[i] = (i < cnt) ? g_wkeys[k*CAPW + i] : 0ull;
        __syncthreads();
        for (int kk = 2; kk <= P; kk <<= 1) {
            for (int j = kk >> 1; j > 0; j >>= 1) {
                for (int i = tid; i < P; i += 256) {
                    int ixj = i ^ j;
                    if (ixj > i) {
                        unsigned long long a = skeys[i], bb = skeys[ixj];
                        bool up = ((i & kk) == 0);
                        if (up ? (a < bb) : (a > bb)) { skeys[i] = bb; skeys[ixj] = a; }
                    }
                }
                __syncthreads();
            }
        }
        int kw = (cnt < 16) ? cnt : 16;
        if (tid == 0) g_kw[k] = kw;
        int w = tid >> 5, l = tid & 31;
        #pragma unroll
        for (int rb = 0; rb < 2; rb++) {
            int r = w + rb*8;
            int rr = (r == 0) ? 0 : (r - 1);
            float v[8]; float s2 = 0.f;
            if (r < kw) {
                int n = key_idx(skeys[rr]);
                int b = n >> 14, p = n & (HW-1);
                const float* base = fw + (size_t)b*C*HW + p;
                #pragma unroll
                for (int i = 0; i < 8; i++) {
                    v[i] = base[(size_t)(l + 32*i)*HW];
                    s2 = fmaf(v[i], v[i], s2);
                }
            } else {
                #pragma unroll
                for (int i = 0; i < 8; i++) v[i] = 0.f;
            }
            #pragma unroll
            for (int o = 16; o; o >>= 1) s2 += __shfl_xor_sync(0xFFFFFFFFu, s2, o);
            float inv = 1.0f / fmaxf(sqrtf(s2), EPSF);
            #pragma unroll
            for (int i = 0; i < 8; i++)
                g_wn[(k*C + l + 32*i)*16 + r] = v[i] * inv;
        }
    } else {
        // ---- strong: radix select top-256 set (unordered) ----
        int k = blk - NCLS;
        int cnt = g_cnt_s[k]; if (cnt > CAPS) cnt = CAPS;
        int need = (cnt < 256) ? cnt : 256;
        for (int i = tid; i < NBINS; i += 256) hist[i] = 0;
        if (tid == 0) { sh_out = 0; sh_bnd = 0; }
        __syncthreads();
        const unsigned long long* src = &g_skeys[k*CAPS];
        for (int i = tid; i < cnt; i += 256) {
            int bin = (int)(src[i] >> 52);
            atomicAdd(&hist[bin], 1);
        }
        __syncthreads();
        { int s = 0;
          #pragma unroll 4
          for (int b2 = 0; b2 < 16; b2++) s += hist[tid*16 + b2];
          gsum[tid] = s; }
        __syncthreads();
        if (tid == 0) {
            int acc = 0, G = 0;
            for (int g = 255; g >= 0; g--) {
                if (acc + gsum[g] >= need) { G = g; break; }
                acc += gsum[g];
            }
            int T = G*16;
            for (int b2 = G*16 + 15; b2 >= G*16; b2--) {
                if (acc + hist[b2] >= need) { T = b2; break; }
                acc += hist[b2];
            }
            sh_T = T; sh_a = acc; sh_m = need - acc;
        }
        __syncthreads();
        int T = sh_T;
        for (int i = tid; i < cnt; i += 256) {
            unsigned long long key = src[i];
            int bin = (int)(key >> 52);
            if (bin > T) {
                int pos = atomicAdd(&sh_out, 1);
                g_sidx[k*256 + pos] = key_idx(key);
            } else if (bin == T) {
                int pos = atomicAdd(&sh_bnd, 1);
                if (pos < BCAP) bkeys[pos] = key;
            }
        }
        __syncthreads();
        int bnd = sh_bnd; if (bnd > BCAP) bnd = BCAP;
        int P = 1; while (P < bnd) P <<= 1;
        for (int i = tid; i < P; i += 256) if (i >= bnd) bkeys[i] = 0ull;
        __syncthreads();
        for (int kk = 2; kk <= P; kk <<= 1) {
            for (int j = kk >> 1; j > 0; j >>= 1) {
                for (int i = tid; i < P; i += 256) {
                    int ixj = i ^ j;
                    if (ixj > i) {
                        unsigned long long a = bkeys[i], bb = bkeys[ixj];
                        bool up = ((i & kk) == 0);
                        if (up ? (a < bb) : (a > bb)) { bkeys[i] = bb; bkeys[ixj] = a; }
                    }
                }
                __syncthreads();
            }
        }
        if (tid < sh_m) g_sidx[k*256 + sh_a + tid] = key_idx(bkeys[tid]);
        if (tid == 0) g_ks[k] = need;
    }
}

// ---------------- K3: loss (R14-proven: grid 21x32, warp-per-slot) ----------
__global__ __launch_bounds__(256) void loss_kernel(const float* __restrict__ fs) {
    int k = blockIdx.x, chunk = blockIdx.y, tid = threadIdx.x;
    __shared__ float swn[C*18];
    __shared__ unsigned smax[16];
    for (int i = tid; i < C*16; i += 256) {
        int c = i >> 4, r = i & 15;
        swn[c*18 + r] = g_wn[k*C*16 + i];
    }
    if (tid < 16) smax[tid] = 0u;
    __syncthreads();

    int ks = g_ks[k];
    int w = tid >> 5, lane = tid & 31;   // warp = slot
    int s = chunk*8 + w;

    float acc[16];
    #pragma unroll
    for (int r = 0; r < 16; r++) acc[r] = 0.f;
    float q = 0.f;
    bool active = (s < ks);
    if (active) {
        int n = g_sidx[k*256 + s];
        int b = n >> 14, p = n & (HW-1);
        const float* base = fs + (size_t)b*C*HW + p;
        #pragma unroll
        for (int cc = 0; cc < 8; cc++) {
            int c = cc*32 + lane;
            float v = base[(size_t)c*HW];
            q = fmaf(v, v, q);
            const float2* row = (const float2*)&swn[c*18];
            #pragma unroll
            for (int g = 0; g < 8; g++) {
                float2 w2 = row[g];
                acc[g*2+0] = fmaf(v, w2.x, acc[g*2+0]);
                acc[g*2+1] = fmaf(v, w2.y, acc[g*2+1]);
            }
        }
    }
    #pragma unroll
    for (int o = 16; o; o >>= 1) {
        q += __shfl_xor_sync(0xFFFFFFFFu, q, o);
        #pragma unroll
        for (int r = 0; r < 16; r++)
            acc[r] += __shfl_xor_sync(0xFFFFFFFFu, acc[r], o);
    }
    if (active && lane == 0) {
        float inv = 1.0f / fmaxf(sqrtf(q), EPSF);
        #pragma unroll
        for (int r = 0; r < 16; r++)
            atomicMax(&smax[r], fenc(acc[r] * inv));
    }
    __syncthreads();
    if (tid < 16 && ks > 0) atomicMax(&g_maxv[k*16 + tid], smax[tid]);
}

// ---------------- K4: finalize (R14-proven parallel reduce + restore) -------
__global__ void final_kernel(const float* __restrict__ bank, float* __restrict__ out,
                             int out_size) {
    __shared__ float sred[256];
    __shared__ int scnt[256];
    int i = blockIdx.x * blockDim.x + threadIdx.x;   // 21 blocks x 256
    int k = blockIdx.x;
    int t = threadIdx.x;

    if (i < NCLS*C && (1 + i) < out_size) {
        int nw = g_cnt_w[k];
        float pv = bank[i];
        float o = pv;
        if (nw > 0) {
            float mean = g_wsum[i] / (float)((nw > 1) ? nw : 1);
            o = 0.99f * pv + 0.01f * mean;
        }
        out[1 + i] = o;
    }

    if (blockIdx.x == 0) {
        float ssum = 0.f;
        int cnt = 0;
        for (int idx = t; idx < NCLS*16; idx += 256) {
            int kk = idx >> 4, r = idx & 15;
            int kw = g_kw[kk], ks = g_ks[kk];
            if (kw > 0 && ks > 0) {
                if (r < kw) ssum += fdec(g_maxv[idx]);
                if (r == 0) cnt += ks;
            }
        }
        sred[t] = ssum;
        scnt[t] = cnt;
        __syncthreads();
        #pragma unroll
        for (int o = 128; o; o >>= 1) {
            if (t < o) { sred[t] += sred[t + o]; scnt[t] += scnt[t + o]; }
            __syncthreads();
        }
        if (t == 0)
            out[0] = (scnt[0] > 0) ? (1.0f - sred[0] / (float)scnt[0]) : 0.0f;
        __syncthreads();
        for (int idx = t; idx < NCLS*16; idx += 256) g_maxv[idx] = 0u;
    }
    __syncthreads();
    if (i < NCLS*C) g_wsum[i] = 0.f;
    if (t == 0) { g_cnt_w[k] = 0; g_cnt_s[k] = 0; }
}

// ---------------- launch ----------------
extern "C" void kernel_launch(void* const* d_in, const int* in_sizes, int n_in,
                              void* d_out, int out_size) {
    const float* fw   = (const float*)d_in[0];
    const float* fs   = (const float*)d_in[1];
    const float* prob = (const float*)d_in[2];
    const float* bank = (const float*)d_in[3];
    const int*   pred = (const int*)d_in[4];
    const int*   ign  = (const int*)d_in[5];
    float* out = (float*)d_out;

    main_kernel<<<NPIX/256, 256>>>(fw, fs, prob, pred, ign, bank);
    select_kernel<<<2*NCLS + NCLS*WCH, 256>>>(fw);
    loss_kernel<<<dim3(NCLS, 32), 256>>>(fs);
    final_kernel<<<(NCLS*C + 255)/256, 256>>>(bank, out, out_size);
}